// round 16
// baseline (speedup 1.0000x reference)
#include <cuda_runtime.h>
#include <cuda_fp16.h>
#include <cstdint>

// ---------------------------------------------------------------------------
// FMoELinearProj via legacy HMMA (mma.sync.m16n8k16.f16), single fp16 digit.
// R15: prepass deleted — GEMM1 rounds x in-loop. Staging registers halved by
// converting fp32->fp16x2 at LOAD time (u32 staging: A 8 regs, B 16 regs vs
// R14's 32). Geometry unchanged from R14 (best): CTA 128x256, 8 warps of
// 64x64, 2-stage smem, occ 1. GEMM1 emits y fp16; GEMM2 pulls via cp.async.
// ---------------------------------------------------------------------------

#define BM 128
#define BN 256
#define NTH 256
#define SROW 80                        // padded smem row: 64B data + 16B pad
#define ATILE (128 * SROW)             // 10240
#define BTILE (256 * SROW)             // 20480
#define OFF_B ATILE
#define STAGEB (ATILE + BTILE)         // 30720
#define BIAS_OFF (2 * STAGEB)          // 61440
#define SMEM_TOTAL (BIAS_OFF + 1024 + 128)

__device__ int  g_off[65];
__device__ int2 g_tiles[1024];
__device__ int  g_ntiles;
__device__ __half g_yh[8192ull * 4096];

// ------------------------------- helpers -----------------------------------
__device__ __forceinline__ uint32_t smem_u32(const void* p) {
    uint32_t a;
    asm("{ .reg .u64 t; cvta.to.shared.u64 t, %1; cvt.u32.u64 %0, t; }"
        : "=r"(a) : "l"(p));
    return a;
}
__device__ __forceinline__ void ldsm4(uint32_t* r, uint32_t addr) {
    asm volatile("ldmatrix.sync.aligned.m8n8.x4.shared.b16 {%0,%1,%2,%3}, [%4];"
                 : "=r"(r[0]), "=r"(r[1]), "=r"(r[2]), "=r"(r[3]) : "r"(addr));
}
__device__ __forceinline__ void mma16816(float* c, const uint32_t* a,
                                         const uint32_t* b) {
    asm volatile(
        "mma.sync.aligned.m16n8k16.row.col.f32.f16.f16.f32 "
        "{%0,%1,%2,%3}, {%4,%5,%6,%7}, {%8,%9}, {%0,%1,%2,%3};"
        : "+f"(c[0]), "+f"(c[1]), "+f"(c[2]), "+f"(c[3])
        : "r"(a[0]), "r"(a[1]), "r"(a[2]), "r"(a[3]), "r"(b[0]), "r"(b[1]));
}
__device__ __forceinline__ void cpa16(uint32_t dst, const void* src,
                                      uint32_t ssize) {
    asm volatile("cp.async.cg.shared.global [%0], [%1], 16, %2;"
                 :: "r"(dst), "l"(src), "r"(ssize) : "memory");
}
#define CP_COMMIT() asm volatile("cp.async.commit_group;" ::: "memory")
#define CP_WAIT0()  asm volatile("cp.async.wait_group 0;" ::: "memory")

__device__ __forceinline__ void sts128(uint32_t a, uint32_t r0, uint32_t r1,
                                       uint32_t r2, uint32_t r3) {
    asm volatile("st.shared.v4.b32 [%0], {%1, %2, %3, %4};"
                 :: "r"(a), "r"(r0), "r"(r1), "r"(r2), "r"(r3) : "memory");
}
__device__ __forceinline__ uint32_t h2rn(float e0, float e1) {
    uint32_t d;
    asm("cvt.rn.f16x2.f32 %0, %1, %2;" : "=r"(d) : "f"(e1), "f"(e0));
    return d;
}
// Load 8 fp32 and convert straight to 4 x fp16x2 (u32) — 4 staging regs.
__device__ __forceinline__ void load_cvt8(const float* p, uint32_t* h) {
    float4 u0 = *(const float4*)p;
    float4 u1 = *(const float4*)(p + 4);
    h[0] = h2rn(u0.x, u0.y);
    h[1] = h2rn(u0.z, u0.w);
    h[2] = h2rn(u1.x, u1.y);
    h[3] = h2rn(u1.z, u1.w);
}

// ------------------------------ setup kernel -------------------------------
__global__ void setup_kernel(const int* __restrict__ counts, int E) {
    if (threadIdx.x == 0 && blockIdx.x == 0) {
        int off = 0, nt = 0;
        for (int e = 0; e < E; ++e) {
            g_off[e] = off;
            int c = counts[e];
            for (int m = 0; m < c; m += BM) { g_tiles[nt].x = e; g_tiles[nt].y = m; ++nt; }
            off += c;
        }
        g_off[E] = off;
        g_ntiles = nt;
    }
}

// ------------------------------ main GEMM kernel ---------------------------
// C[row, n] = sum_k A[row, k] * B[e, n, k] (+ bias).
// A_F16: A pre-rounded fp16 (g_yh) via cp.async; else fp32, cvt at load.
// F16_OUT: write C as fp16 into g_yh; else fp32 to Cf.
template <bool ADD_BIAS, bool A_F16, bool F16_OUT>
__global__ __launch_bounds__(NTH, 1)
void moe_hmma(const float* __restrict__ Af,
              const __half* __restrict__ Ah,
              const float* __restrict__ Bf,
              const float* __restrict__ bias, float* __restrict__ Cf,
              int K, int N)
{
    const int tile = blockIdx.y;
    if (tile >= g_ntiles) return;
    const int e    = g_tiles[tile].x;
    const int m0   = g_tiles[tile].y;
    const int row0 = g_off[e] + m0;
    int mrows = g_off[e + 1] - g_off[e] - m0;
    if (mrows > BM) mrows = BM;
    const int n0 = blockIdx.x * BN;

    extern __shared__ char smem[];
    const uint32_t sb = smem_u32(smem);
    const int tid = threadIdx.x, wid = tid >> 5, lane = tid & 31;
    const int warp_m = wid & 1, warp_n = wid >> 1;   // 2 x 4 warps of 64x64

    if (ADD_BIAS && tid < 64)
        ((float4*)(smem + BIAS_OFF))[tid] =
            *(const float4*)&bias[(size_t)e * N + n0 + tid * 4];

    // ---- A: 2 chunks per thread (128 rows x 4 chunks) ----
    const int rA0 = tid >> 2;                 // 0..63
    const int rA1 = (tid + 256) >> 2;         // 64..127
    const uint32_t cby = (uint32_t)(tid & 3) * 16;
    const uint32_t sdA0 = (uint32_t)(rA0 * SROW) + cby;
    const uint32_t sdA1 = (uint32_t)(rA1 * SROW) + cby;
    const bool aok0 = rA0 < mrows, aok1 = rA1 < mrows;
    const uint32_t szA0 = aok0 ? 16u : 0u, szA1 = aok1 ? 16u : 0u;
    const int ccol = (tid & 3) * 8;           // element offset in k-tile
    const char*  Ahp0 = (const char*)(Ah + (size_t)(row0 + rA0) * K + ccol);
    const char*  Ahp1 = (const char*)(Ah + (size_t)(row0 + rA1) * K + ccol);
    const float* Afp0 = Af + (size_t)(row0 + rA0) * K + ccol;
    const float* Afp1 = Af + (size_t)(row0 + rA1) * K + ccol;

    // ---- B: 4 row chunks per thread (256 rows x 4 chunks) ----
    const int rB = tid >> 2;                  // base row, +64 per q
    const uint32_t sdB = (uint32_t)(rB * SROW) + cby;
    const float* Bbase = Bf + ((size_t)e * N + n0 + rB) * K + ccol;
    const size_t Bstep = (size_t)64 * K;

    // -------- prologue: stage kt=0 into buffer 0 --------
    if (A_F16) {
        cpa16(sb + sdA0, Ahp0, szA0);
        cpa16(sb + sdA1, Ahp1, szA1);
        CP_COMMIT();
    } else {
        uint32_t ha0[4] = {0, 0, 0, 0}, ha1[4] = {0, 0, 0, 0};
        if (aok0) load_cvt8(Afp0, ha0);
        if (aok1) load_cvt8(Afp1, ha1);
        sts128(sb + sdA0, ha0[0], ha0[1], ha0[2], ha0[3]);
        sts128(sb + sdA1, ha1[0], ha1[1], ha1[2], ha1[3]);
    }
#pragma unroll
    for (int q = 0; q < 4; ++q) {
        uint32_t hb[4];
        load_cvt8(Bbase + (size_t)q * Bstep, hb);
        sts128(sb + OFF_B + sdB + (uint32_t)q * (64 * SROW),
               hb[0], hb[1], hb[2], hb[3]);
    }
    if (A_F16) CP_WAIT0();
    __syncthreads();

    float acc[4][8][4];
#pragma unroll
    for (int mi = 0; mi < 4; ++mi)
#pragma unroll
        for (int nj = 0; nj < 8; ++nj)
#pragma unroll
            for (int q = 0; q < 4; ++q) acc[mi][nj][q] = 0.f;

    const uint32_t a_off = (uint32_t)(warp_m * 64 + (lane & 15)) * SROW +
                           ((lane >> 4) * 16);
    const uint32_t b_off = (uint32_t)(warp_n * 64 + (lane & 7) +
                                      ((lane >> 4) & 1) * 8) * SROW +
                           (((lane >> 3) & 1) * 16);

    const int nk = K >> 5;
    for (int kt = 0; kt < nk; ++kt) {
        const uint32_t stg  = sb + (uint32_t)(kt & 1) * STAGEB;
        const uint32_t nstg = sb + (uint32_t)((kt + 1) & 1) * STAGEB;
        const bool more = (kt + 1 < nk);
        const int ko = (kt + 1) * 32;

        // Prefetch kt+1: A via cp.async or load+cvt to u32; B load+cvt to u32.
        uint32_t ha0[4], ha1[4], hb[4][4];
        if (more) {
            if (A_F16) {
                cpa16(nstg + sdA0, Ahp0 + ko * 2, szA0);
                cpa16(nstg + sdA1, Ahp1 + ko * 2, szA1);
                CP_COMMIT();
            } else {
                ha0[0] = ha0[1] = ha0[2] = ha0[3] = 0u;
                ha1[0] = ha1[1] = ha1[2] = ha1[3] = 0u;
                if (aok0) load_cvt8(Afp0 + ko, ha0);
                if (aok1) load_cvt8(Afp1 + ko, ha1);
            }
#pragma unroll
            for (int q = 0; q < 4; ++q)
                load_cvt8(Bbase + (size_t)q * Bstep + ko, hb[q]);
        }

        // ------------------------- MMA phase (2 x k16) ----------------------
#pragma unroll
        for (int k16 = 0; k16 < 2; ++k16) {
            const uint32_t kb = k16 * 32;
            uint32_t ah[4][4], bh[4][4];
#pragma unroll
            for (int mi = 0; mi < 4; ++mi)
                ldsm4(ah[mi], stg + a_off + kb + mi * 16 * SROW);
#pragma unroll
            for (int bj = 0; bj < 4; ++bj)
                ldsm4(bh[bj], stg + OFF_B + b_off + kb + bj * 16 * SROW);
#pragma unroll
            for (int mi = 0; mi < 4; ++mi)
#pragma unroll
                for (int nj = 0; nj < 8; ++nj)
                    mma16816(acc[mi][nj], ah[mi], &bh[nj >> 1][(nj & 1) * 2]);
        }

        if (more) {
            if (!A_F16) {
                sts128(nstg + sdA0, ha0[0], ha0[1], ha0[2], ha0[3]);
                sts128(nstg + sdA1, ha1[0], ha1[1], ha1[2], ha1[3]);
            }
#pragma unroll
            for (int q = 0; q < 4; ++q)
                sts128(nstg + OFF_B + sdB + (uint32_t)q * (64 * SROW),
                       hb[q][0], hb[q][1], hb[q][2], hb[q][3]);
            if (A_F16) CP_WAIT0();
        }
        __syncthreads();
    }

    // ------------------------------ epilogue --------------------------------
    const float* bs = (const float*)(smem + BIAS_OFF);
    uint32_t* yh32 = (uint32_t*)g_yh;
#pragma unroll
    for (int mi = 0; mi < 4; ++mi) {
        const int r = warp_m * 64 + mi * 16 + (lane >> 2);
#pragma unroll
        for (int nj = 0; nj < 8; ++nj) {
            const int c = warp_n * 64 + nj * 8 + (lane & 3) * 2;
            float2 v0 = make_float2(acc[mi][nj][0], acc[mi][nj][1]);
            float2 v1 = make_float2(acc[mi][nj][2], acc[mi][nj][3]);
            if (ADD_BIAS) {
                const float b0 = bs[c], b1 = bs[c + 1];
                v0.x += b0; v0.y += b1;
                v1.x += b0; v1.y += b1;
            }
            if (F16_OUT) {
                if (r < mrows) {
                    const size_t ix = ((size_t)(row0 + r) * N + n0 + c) >> 1;
                    yh32[ix] = h2rn(v0.x, v0.y);
                }
                if (r + 8 < mrows) {
                    const size_t ix = ((size_t)(row0 + r + 8) * N + n0 + c) >> 1;
                    yh32[ix] = h2rn(v1.x, v1.y);
                }
            } else {
                if (r < mrows)
                    *(float2*)&Cf[(size_t)(row0 + r) * N + n0 + c] = v0;
                if (r + 8 < mrows)
                    *(float2*)&Cf[(size_t)(row0 + r + 8) * N + n0 + c] = v1;
            }
        }
    }
}

// ------------------------------- launch -------------------------------------
extern "C" void kernel_launch(void* const* d_in, const int* in_sizes, int n_in,
                              void* d_out, int out_size) {
    const float* inp  = (const float*)d_in[0];
    const int*   cnt  = (const int*)  d_in[1];
    const float* wgt  = (const float*)d_in[2];
    const float* bias = (const float*)d_in[3];
    const float* comp = (const float*)d_in[4];
    float* out = (float*)d_out;

    const int E     = in_sizes[1];
    const int D_out = in_sizes[3] / E;
    const int D_in  = in_sizes[2] / in_sizes[3];
    const int T     = in_sizes[0] / D_in;
    const int S     = in_sizes[4] / in_sizes[3];
    const int maxtiles = T / BM + E;

    cudaFuncSetAttribute(moe_hmma<true, false, true>,
                         cudaFuncAttributeMaxDynamicSharedMemorySize, SMEM_TOTAL);
    cudaFuncSetAttribute(moe_hmma<false, true, false>,
                         cudaFuncAttributeMaxDynamicSharedMemorySize, SMEM_TOTAL);

    __half* yh;
    cudaGetSymbolAddress((void**)&yh, g_yh);

    setup_kernel<<<1, 1>>>(cnt, E);

    // GEMM1: y = x @ W^T + b  (x fp32 cvt-at-load; W cvt-at-load; y fp16)
    moe_hmma<true, false, true><<<dim3(D_out / BN, maxtiles), NTH, SMEM_TOTAL>>>(
        inp, nullptr, wgt, bias, nullptr, D_in, D_out);
    // GEMM2: out = y @ C^T  (y fp16 via cp.async; comp cvt-at-load)
    moe_hmma<false, true, false><<<dim3(S / BN, maxtiles), NTH, SMEM_TOTAL>>>(
        nullptr, yh, comp, nullptr, out, D_out, S);
}

// round 17
// speedup vs baseline: 1.4107x; 1.4107x over previous
#include <cuda_runtime.h>
#include <cuda_fp16.h>
#include <cstdint>

// ---------------------------------------------------------------------------
// FMoELinearProj via legacy HMMA (mma.sync.m16n8k16.f16), single fp16 digit.
// R16: revert to R14 (best: 420.3 us) — CTA 128x256, 8 warps of 64x64,
// 2-stage smem, occ 1; A fp16 via cp.async (x pre-rounded by prepass, y fp16
// from GEMM1); B staged as fp32 regs, converted AT STORE time (R15's
// cvt-at-load exposed LDG latency — reverted). One change vs R14: the serial
// setup scan is folded into thread (0,0) of the prepass kernel (-1 launch).
// ---------------------------------------------------------------------------

#define BM 128
#define BN 256
#define NTH 256
#define SROW 80                        // padded smem row: 64B data + 16B pad
#define ATILE (128 * SROW)             // 10240
#define BTILE (256 * SROW)             // 20480
#define OFF_B ATILE
#define STAGEB (ATILE + BTILE)         // 30720
#define BIAS_OFF (2 * STAGEB)          // 61440
#define SMEM_TOTAL (BIAS_OFF + 1024 + 128)

__device__ int  g_off[65];
__device__ int2 g_tiles[1024];
__device__ int  g_ntiles;
__device__ __half g_xh[8192ull * 1024];
__device__ __half g_yh[8192ull * 4096];

// ------------------------------- helpers -----------------------------------
__device__ __forceinline__ uint32_t smem_u32(const void* p) {
    uint32_t a;
    asm("{ .reg .u64 t; cvta.to.shared.u64 t, %1; cvt.u32.u64 %0, t; }"
        : "=r"(a) : "l"(p));
    return a;
}
__device__ __forceinline__ void ldsm4(uint32_t* r, uint32_t addr) {
    asm volatile("ldmatrix.sync.aligned.m8n8.x4.shared.b16 {%0,%1,%2,%3}, [%4];"
                 : "=r"(r[0]), "=r"(r[1]), "=r"(r[2]), "=r"(r[3]) : "r"(addr));
}
__device__ __forceinline__ void mma16816(float* c, const uint32_t* a,
                                         const uint32_t* b) {
    asm volatile(
        "mma.sync.aligned.m16n8k16.row.col.f32.f16.f16.f32 "
        "{%0,%1,%2,%3}, {%4,%5,%6,%7}, {%8,%9}, {%0,%1,%2,%3};"
        : "+f"(c[0]), "+f"(c[1]), "+f"(c[2]), "+f"(c[3])
        : "r"(a[0]), "r"(a[1]), "r"(a[2]), "r"(a[3]), "r"(b[0]), "r"(b[1]));
}
__device__ __forceinline__ void cpa16(uint32_t dst, const void* src,
                                      uint32_t ssize) {
    asm volatile("cp.async.cg.shared.global [%0], [%1], 16, %2;"
                 :: "r"(dst), "l"(src), "r"(ssize) : "memory");
}
#define CP_COMMIT() asm volatile("cp.async.commit_group;" ::: "memory")
#define CP_WAIT0()  asm volatile("cp.async.wait_group 0;" ::: "memory")

__device__ __forceinline__ void sts128(uint32_t a, uint32_t r0, uint32_t r1,
                                       uint32_t r2, uint32_t r3) {
    asm volatile("st.shared.v4.b32 [%0], {%1, %2, %3, %4};"
                 :: "r"(a), "r"(r0), "r"(r1), "r"(r2), "r"(r3) : "memory");
}
__device__ __forceinline__ uint32_t h2rn(float e0, float e1) {
    uint32_t d;
    asm("cvt.rn.f16x2.f32 %0, %1, %2;" : "=r"(d) : "f"(e1), "f"(e0));
    return d;
}
__device__ __forceinline__ void round_sts(uint32_t dst, float4 u0, float4 u1) {
    sts128(dst, h2rn(u0.x, u0.y), h2rn(u0.z, u0.w),
                h2rn(u1.x, u1.y), h2rn(u1.z, u1.w));
}

// ------------------- x -> fp16 prepass + fused tile setup ------------------
__global__ void round_kernel(const float* __restrict__ src,
                             __half* __restrict__ dst, long n,
                             const int* __restrict__ counts, int E) {
    if (blockIdx.x == 0 && threadIdx.x == 0) {
        int off = 0, nt = 0;
        for (int e = 0; e < E; ++e) {
            g_off[e] = off;
            int c = counts[e];
            for (int m = 0; m < c; m += BM) { g_tiles[nt].x = e; g_tiles[nt].y = m; ++nt; }
            off += c;
        }
        g_off[E] = off;
        g_ntiles = nt;
    }
    long stride = (long)gridDim.x * blockDim.x * 4;
    for (long i = ((long)blockIdx.x * blockDim.x + threadIdx.x) * 4; i < n;
         i += stride) {
        float4 v = *(const float4*)(src + i);
        uint2 h;
        h.x = h2rn(v.x, v.y);
        h.y = h2rn(v.z, v.w);
        *(uint2*)(dst + i) = h;
    }
}

// ------------------------------ main GEMM kernel ---------------------------
// C[row, n] = sum_k A[row, k] * B[e, n, k] (+ bias).
// A: fp16 (g_xh or g_yh) via cp.async. B: fp32 regs, converted at store.
// F16_OUT: write C as fp16 into g_yh; else fp32 to Cf.
template <bool ADD_BIAS, bool F16_OUT>
__global__ __launch_bounds__(NTH, 1)
void moe_hmma(const __half* __restrict__ Ah,
              const float* __restrict__ Bf,
              const float* __restrict__ bias, float* __restrict__ Cf,
              int K, int N)
{
    const int tile = blockIdx.y;
    if (tile >= g_ntiles) return;
    const int e    = g_tiles[tile].x;
    const int m0   = g_tiles[tile].y;
    const int row0 = g_off[e] + m0;
    int mrows = g_off[e + 1] - g_off[e] - m0;
    if (mrows > BM) mrows = BM;
    const int n0 = blockIdx.x * BN;

    extern __shared__ char smem[];
    const uint32_t sb = smem_u32(smem);
    const int tid = threadIdx.x, wid = tid >> 5, lane = tid & 31;
    const int warp_m = wid & 1, warp_n = wid >> 1;   // 2 x 4 warps of 64x64

    if (ADD_BIAS && tid < 64)
        ((float4*)(smem + BIAS_OFF))[tid] =
            *(const float4*)&bias[(size_t)e * N + n0 + tid * 4];

    // ---- A: 2 cp.async chunks per thread (128 rows x 4 chunks) ----
    const int rA0 = tid >> 2;                 // 0..63
    const int rA1 = (tid + 256) >> 2;         // 64..127
    const uint32_t cby = (uint32_t)(tid & 3) * 16;
    const uint32_t sdA0 = (uint32_t)(rA0 * SROW) + cby;
    const uint32_t sdA1 = (uint32_t)(rA1 * SROW) + cby;
    const uint32_t szA0 = (rA0 < mrows) ? 16u : 0u;
    const uint32_t szA1 = (rA1 < mrows) ? 16u : 0u;
    const int ccol = (tid & 3) * 8;           // element offset in k-tile
    const char* Ahp0 = (const char*)(Ah + (size_t)(row0 + rA0) * K + ccol);
    const char* Ahp1 = (const char*)(Ah + (size_t)(row0 + rA1) * K + ccol);

    // ---- B: 4 row chunks per thread (256 rows x 4 chunks) ----
    const int rB = tid >> 2;                  // base row, +64 per q
    const uint32_t sdB = (uint32_t)(rB * SROW) + cby;
    const float* Bbase = Bf + ((size_t)e * N + n0 + rB) * K + ccol;
    const size_t Bstep = (size_t)64 * K;

    // -------- prologue: stage kt=0 into buffer 0 --------
    cpa16(sb + sdA0, Ahp0, szA0);
    cpa16(sb + sdA1, Ahp1, szA1);
    CP_COMMIT();
#pragma unroll
    for (int q = 0; q < 4; ++q) {
        const float* bp = Bbase + (size_t)q * Bstep;
        float4 u0 = *(const float4*)bp;
        float4 u1 = *(const float4*)(bp + 4);
        round_sts(sb + OFF_B + sdB + (uint32_t)q * (64 * SROW), u0, u1);
    }
    CP_WAIT0();
    __syncthreads();

    float acc[4][8][4];
#pragma unroll
    for (int mi = 0; mi < 4; ++mi)
#pragma unroll
        for (int nj = 0; nj < 8; ++nj)
#pragma unroll
            for (int q = 0; q < 4; ++q) acc[mi][nj][q] = 0.f;

    const uint32_t a_off = (uint32_t)(warp_m * 64 + (lane & 15)) * SROW +
                           ((lane >> 4) * 16);
    const uint32_t b_off = (uint32_t)(warp_n * 64 + (lane & 7) +
                                      ((lane >> 4) & 1) * 8) * SROW +
                           (((lane >> 3) & 1) * 16);

    const int nk = K >> 5;
    for (int kt = 0; kt < nk; ++kt) {
        const uint32_t stg  = sb + (uint32_t)(kt & 1) * STAGEB;
        const uint32_t nstg = sb + (uint32_t)((kt + 1) & 1) * STAGEB;
        const bool more = (kt + 1 < nk);
        const int ko = (kt + 1) * 32;

        float4 b0[4], b1[4];
        if (more) {
            cpa16(nstg + sdA0, Ahp0 + ko * 2, szA0);
            cpa16(nstg + sdA1, Ahp1 + ko * 2, szA1);
            CP_COMMIT();
#pragma unroll
            for (int q = 0; q < 4; ++q) {
                const float* bp = Bbase + (size_t)q * Bstep + ko;
                b0[q] = *(const float4*)bp;
                b1[q] = *(const float4*)(bp + 4);
            }
        }

        // ------------------------- MMA phase (2 x k16) ----------------------
#pragma unroll
        for (int k16 = 0; k16 < 2; ++k16) {
            const uint32_t kb = k16 * 32;
            uint32_t ah[4][4], bh[4][4];
#pragma unroll
            for (int mi = 0; mi < 4; ++mi)
                ldsm4(ah[mi], stg + a_off + kb + mi * 16 * SROW);
#pragma unroll
            for (int bj = 0; bj < 4; ++bj)
                ldsm4(bh[bj], stg + OFF_B + b_off + kb + bj * 16 * SROW);
#pragma unroll
            for (int mi = 0; mi < 4; ++mi)
#pragma unroll
                for (int nj = 0; nj < 8; ++nj)
                    mma16816(acc[mi][nj], ah[mi], &bh[nj >> 1][(nj & 1) * 2]);
        }

        if (more) {
#pragma unroll
            for (int q = 0; q < 4; ++q)
                round_sts(nstg + OFF_B + sdB + (uint32_t)q * (64 * SROW),
                          b0[q], b1[q]);
            CP_WAIT0();
        }
        __syncthreads();
    }

    // ------------------------------ epilogue --------------------------------
    const float* bs = (const float*)(smem + BIAS_OFF);
    uint32_t* yh32 = (uint32_t*)g_yh;
#pragma unroll
    for (int mi = 0; mi < 4; ++mi) {
        const int r = warp_m * 64 + mi * 16 + (lane >> 2);
#pragma unroll
        for (int nj = 0; nj < 8; ++nj) {
            const int c = warp_n * 64 + nj * 8 + (lane & 3) * 2;
            float2 v0 = make_float2(acc[mi][nj][0], acc[mi][nj][1]);
            float2 v1 = make_float2(acc[mi][nj][2], acc[mi][nj][3]);
            if (ADD_BIAS) {
                const float b0 = bs[c], b1 = bs[c + 1];
                v0.x += b0; v0.y += b1;
                v1.x += b0; v1.y += b1;
            }
            if (F16_OUT) {
                if (r < mrows) {
                    const size_t ix = ((size_t)(row0 + r) * N + n0 + c) >> 1;
                    yh32[ix] = h2rn(v0.x, v0.y);
                }
                if (r + 8 < mrows) {
                    const size_t ix = ((size_t)(row0 + r + 8) * N + n0 + c) >> 1;
                    yh32[ix] = h2rn(v1.x, v1.y);
                }
            } else {
                if (r < mrows)
                    *(float2*)&Cf[(size_t)(row0 + r) * N + n0 + c] = v0;
                if (r + 8 < mrows)
                    *(float2*)&Cf[(size_t)(row0 + r + 8) * N + n0 + c] = v1;
            }
        }
    }
}

// ------------------------------- launch -------------------------------------
extern "C" void kernel_launch(void* const* d_in, const int* in_sizes, int n_in,
                              void* d_out, int out_size) {
    const float* inp  = (const float*)d_in[0];
    const int*   cnt  = (const int*)  d_in[1];
    const float* wgt  = (const float*)d_in[2];
    const float* bias = (const float*)d_in[3];
    const float* comp = (const float*)d_in[4];
    float* out = (float*)d_out;

    const int E     = in_sizes[1];
    const int D_out = in_sizes[3] / E;
    const int D_in  = in_sizes[2] / in_sizes[3];
    const int T     = in_sizes[0] / D_in;
    const int S     = in_sizes[4] / in_sizes[3];
    const int maxtiles = T / BM + E;

    cudaFuncSetAttribute(moe_hmma<true, true>,
                         cudaFuncAttributeMaxDynamicSharedMemorySize, SMEM_TOTAL);
    cudaFuncSetAttribute(moe_hmma<false, false>,
                         cudaFuncAttributeMaxDynamicSharedMemorySize, SMEM_TOTAL);

    __half *xh, *yh;
    cudaGetSymbolAddress((void**)&xh, g_xh);
    cudaGetSymbolAddress((void**)&yh, g_yh);

    // prepass: round x to fp16 + build tile worklist (fused, one launch)
    round_kernel<<<296, 256>>>(inp, xh, (long)in_sizes[0], cnt, E);

    // GEMM1: y = x @ W^T + b  (x fp16 via cp.async; W rounded in-loop; y fp16)
    moe_hmma<true, true><<<dim3(D_out / BN, maxtiles), NTH, SMEM_TOTAL>>>(
        xh, wgt, bias, nullptr, D_in, D_out);
    // GEMM2: out = y @ C^T  (y fp16 via cp.async; comp rounded in-loop)
    moe_hmma<false, false><<<dim3(S / BN, maxtiles), NTH, SMEM_TOTAL>>>(
        yh, comp, nullptr, out, D_out, S);
}